// round 16
// baseline (speedup 1.0000x reference)
#include <cuda_runtime.h>
#include <cuda_bf16.h>
#include <cuda_fp16.h>
#include <stdint.h>

#define Bb 4
#define Nn 2048
#define Mm 2048
#define Cc 512
#define Hh 8
#define DHd 64
#define LOG2E 1.4426950408889634f

// ---------------- static scratch (no allocations allowed) ----------------
__device__ __half g_qhi[Bb*Hh*Nn*DHd];   // [bh][n][dh], fp16 hi, pre-scaled by 1/8
__device__ __half g_qlo[Bb*Hh*Nn*DHd];   // fp16 lo
__device__ __half g_k  [Bb*Hh*Mm*DHd];   // [bh][m][dh], SINGLE fp16, pre-scaled kw*log2e
__device__ __half g_vhi[Bb*Hh*DHd*Mm];   // TRANSPOSED [bh][dh][m], fp16 hi
__device__ __half g_vlo[Bb*Hh*DHd*Mm];   // fp16 lo
__device__ float  g_inv[Bb*Hh*Nn];       // 1/rowsum

// ---------------- helpers ----------------
__device__ __forceinline__ void mma_bf16(float c[4], const uint32_t a[4], const uint32_t b[2]) {
    asm volatile(
        "mma.sync.aligned.m16n8k16.row.col.f32.bf16.bf16.f32 "
        "{%0,%1,%2,%3}, {%4,%5,%6,%7}, {%8,%9}, {%0,%1,%2,%3};\n"
        : "+f"(c[0]), "+f"(c[1]), "+f"(c[2]), "+f"(c[3])
        : "r"(a[0]), "r"(a[1]), "r"(a[2]), "r"(a[3]), "r"(b[0]), "r"(b[1]));
}

__device__ __forceinline__ void mma_f16(float c[4], const uint32_t a[4], const uint32_t b[2]) {
    asm volatile(
        "mma.sync.aligned.m16n8k16.row.col.f32.f16.f16.f32 "
        "{%0,%1,%2,%3}, {%4,%5,%6,%7}, {%8,%9}, {%0,%1,%2,%3};\n"
        : "+f"(c[0]), "+f"(c[1]), "+f"(c[2]), "+f"(c[3])
        : "r"(a[0]), "r"(a[1]), "r"(a[2]), "r"(a[3]), "r"(b[0]), "r"(b[1]));
}

__device__ __forceinline__ void split2(float x, __nv_bfloat16 &hi, __nv_bfloat16 &lo) {
    hi = __float2bfloat16_rn(x);
    lo = __float2bfloat16_rn(x - __bfloat162float(hi));
}

__device__ __forceinline__ void split2h(float x, __half &hi, __half &lo) {
    hi = __float2half_rn(x);
    lo = __float2half_rn(x - __half2float(hi));
}

__device__ __forceinline__ uint32_t pk2(__nv_bfloat16 a, __nv_bfloat16 b) {
    return (uint32_t)__bfloat16_as_ushort(a) | ((uint32_t)__bfloat16_as_ushort(b) << 16);
}

__device__ __forceinline__ uint32_t pk2h(__half a, __half b) {
    return (uint32_t)__half_as_ushort(a) | ((uint32_t)__half_as_ushort(b) << 16);
}

// guaranteed MUFU.EX2
__device__ __forceinline__ float ex2f(float x) {
    float r;
    asm("ex2.approx.ftz.f32 %0, %1;" : "=f"(r) : "f"(x));
    return r;
}

// 16B async copy gmem -> smem (LDGSTS)
__device__ __forceinline__ void cpa16(void* smem, const void* gmem) {
    uint32_t s = (uint32_t)__cvta_generic_to_shared(smem);
    asm volatile("cp.async.cg.shared.global [%0], [%1], 16;" :: "r"(s), "l"(gmem));
}

// ---------------- K1: fused projections (X@W + b), bf16-split mma ----------------
// grid: (64, 8, 3)  block: 256.  Internal GEMM unchanged; outputs fp16-coded.
__global__ __launch_bounds__(256) void proj_kernel(
    const float* __restrict__ xq, const float* __restrict__ xk, const float* __restrict__ xv,
    const float* __restrict__ Wq, const float* __restrict__ bq,
    const float* __restrict__ Wk, const float* __restrict__ bk,
    const float* __restrict__ Wv, const float* __restrict__ bv,
    const float* __restrict__ kw)
{
    const float* X; const float* W; const float* bias;
    int z = blockIdx.z;
    if (z == 0)      { X = xq; W = Wq; bias = bq; }
    else if (z == 1) { X = xk; W = Wk; bias = bk; }
    else             { X = xv; W = Wv; bias = bv; }

    __shared__ __nv_bfloat16 Ahi[128][40], Alo[128][40];   // [row][k], k-chunk 32, pad 8
    __shared__ __nv_bfloat16 Bshi[64][40], Bslo[64][40];   // [col][k] transposed

    int tid = threadIdx.x, lane = tid & 31, warp = tid >> 5;
    int row0 = blockIdx.x * 128;
    int col0 = blockIdx.y * 64;
    int wr = (warp >> 1) * 32, wc = (warp & 1) * 32;
    int qr = lane >> 2, qc2 = (lane & 3) * 2;

    float acc[2][4][4];
#pragma unroll
    for (int m = 0; m < 2; m++)
#pragma unroll
        for (int n = 0; n < 4; n++)
#pragma unroll
            for (int e = 0; e < 4; e++) acc[m][n][e] = 0.0f;

    for (int kc = 0; kc < Cc; kc += 32) {
#pragma unroll
        for (int i = tid; i < 128*8; i += 256) {
            int r = i >> 3, c4 = (i & 7) * 4;
            float4 v = *(const float4*)&X[(size_t)(row0 + r)*Cc + kc + c4];
            __nv_bfloat16 h0,l0,h1,l1,h2,l2,h3,l3;
            split2(v.x, h0, l0); split2(v.y, h1, l1);
            split2(v.z, h2, l2); split2(v.w, h3, l3);
            uint2 th; th.x = pk2(h0,h1); th.y = pk2(h2,h3);
            uint2 tl; tl.x = pk2(l0,l1); tl.y = pk2(l2,l3);
            *(uint2*)&Ahi[r][c4] = th;
            *(uint2*)&Alo[r][c4] = tl;
        }
#pragma unroll
        for (int it = 0; it < 2; it++) {
            int slot = tid + it*256;
            int col = slot & 63, kk0 = (slot >> 6) * 4;
            __nv_bfloat16 h0,l0,h1,l1,h2,l2,h3,l3;
            float v0 = W[(size_t)(kc+kk0+0)*Cc + col0 + col];
            float v1 = W[(size_t)(kc+kk0+1)*Cc + col0 + col];
            float v2 = W[(size_t)(kc+kk0+2)*Cc + col0 + col];
            float v3 = W[(size_t)(kc+kk0+3)*Cc + col0 + col];
            split2(v0, h0, l0); split2(v1, h1, l1);
            split2(v2, h2, l2); split2(v3, h3, l3);
            uint2 th; th.x = pk2(h0,h1); th.y = pk2(h2,h3);
            uint2 tl; tl.x = pk2(l0,l1); tl.y = pk2(l2,l3);
            *(uint2*)&Bshi[col][kk0] = th;
            *(uint2*)&Bslo[col][kk0] = tl;
        }
        __syncthreads();
#pragma unroll
        for (int ks = 0; ks < 2; ks++) {
            int kb = ks*16 + qc2;
            uint32_t a_hi[2][4], a_lo[2][4];
#pragma unroll
            for (int m = 0; m < 2; m++) {
                int r = wr + m*16 + qr;
                a_hi[m][0] = *(const uint32_t*)&Ahi[r][kb];
                a_hi[m][1] = *(const uint32_t*)&Ahi[r+8][kb];
                a_hi[m][2] = *(const uint32_t*)&Ahi[r][kb+8];
                a_hi[m][3] = *(const uint32_t*)&Ahi[r+8][kb+8];
                a_lo[m][0] = *(const uint32_t*)&Alo[r][kb];
                a_lo[m][1] = *(const uint32_t*)&Alo[r+8][kb];
                a_lo[m][2] = *(const uint32_t*)&Alo[r][kb+8];
                a_lo[m][3] = *(const uint32_t*)&Alo[r+8][kb+8];
            }
#pragma unroll
            for (int nf = 0; nf < 4; nf++) {
                int cn = wc + nf*8 + qr;
                uint32_t b_hi[2], b_lo[2];
                b_hi[0] = *(const uint32_t*)&Bshi[cn][kb];
                b_hi[1] = *(const uint32_t*)&Bshi[cn][kb+8];
                b_lo[0] = *(const uint32_t*)&Bslo[cn][kb];
                b_lo[1] = *(const uint32_t*)&Bslo[cn][kb+8];
#pragma unroll
                for (int m = 0; m < 2; m++) {
                    mma_bf16(acc[m][nf], a_hi[m], b_hi);
                    mma_bf16(acc[m][nf], a_hi[m], b_lo);
                    mma_bf16(acc[m][nf], a_lo[m], b_hi);
                }
            }
        }
        __syncthreads();
    }

    int h = blockIdx.y;
#pragma unroll
    for (int m = 0; m < 2; m++) {
#pragma unroll
        for (int e = 0; e < 2; e++) {
            int rg = row0 + wr + m*16 + qr + e*8;
            int bb = rg >> 11, sq = rg & 2047;
            float rsc;
            if (z == 0)      rsc = 0.125f;
            else if (z == 1) rsc = kw[bb*Mm + sq] * LOG2E;
            else             rsc = 1.0f;
#pragma unroll
            for (int nf = 0; nf < 4; nf++) {
                int d = wc + nf*8 + qc2;
                float v0 = (acc[m][nf][e*2+0] + bias[col0+d])   * rsc;
                float v1 = (acc[m][nf][e*2+1] + bias[col0+d+1]) * rsc;
                if (z == 0) {
                    size_t o = ((size_t)((bb*Hh + h)*2048 + sq))*64 + d;
                    __half h0,l0,h1,l1;
                    split2h(v0, h0, l0); split2h(v1, h1, l1);
                    *(uint32_t*)&g_qhi[o] = pk2h(h0, h1);
                    *(uint32_t*)&g_qlo[o] = pk2h(l0, l1);
                } else if (z == 1) {
                    size_t o = ((size_t)((bb*Hh + h)*2048 + sq))*64 + d;
                    *(uint32_t*)&g_k[o] = pk2h(__float2half_rn(v0), __float2half_rn(v1));
                } else {
                    // transposed: [bh][dh][m], fp16 hi/lo
                    size_t o = ((size_t)((bb*Hh + h)*64 + d))*2048 + sq;
                    __half h0,l0,h1,l1;
                    split2h(v0, h0, l0); split2h(v1, h1, l1);
                    g_vhi[o] = h0; g_vhi[o + 2048] = h1;
                    g_vlo[o] = l0; g_vlo[o + 2048] = l1;
                }
            }
        }
    }
}

// ---------------- K2: fused attention, fp16 datapath, 4 CTAs/SM ------
// grid: (h 8, n-blocks 32, b 4) = 1024 CTAs, block 128 (4 warps x 16 rows = 64 q rows).
// QK: q fp16 hi/lo x K single fp16 = 2 MMAs.  AV: p single fp16 x V fp16 hi/lo = 2 MMAs.
// out_attn still receives fp32 p (attn output precision preserved).
// launch_bounds(128,4): 16 warps/SM; smem 4x55808 = 223KB fits the 228KB carveout.
#define TILE_B (64*72*2)        // one [64][72] fp16 buffer = 9216 B
#define NSTG 2
__global__ __launch_bounds__(128, 4) void attn_kernel(
    const int* __restrict__ kmask, const float* __restrict__ af,
    const int* __restrict__ amask,
    float* __restrict__ out_hidden, float* __restrict__ out_attn)
{
    extern __shared__ char dsm[];
    __half (*Ks)[64][72]  = (__half(*)[64][72])(dsm);
    __half (*Vth)[64][72] = (__half(*)[64][72])(dsm + NSTG*TILE_B);
    __half (*Vtl)[64][72] = (__half(*)[64][72])(dsm + 2*NSTG*TILE_B);
    int* s_km = (int*)(dsm + 3*NSTG*TILE_B);      // [NSTG][64]

    int tid = threadIdx.x, lane = tid & 31, warp = tid >> 5;
    int qr = lane >> 2, qc2 = (lane & 3) * 2;
    int h = blockIdx.x, b = blockIdx.z;
    int bh = b*Hh + h;
    int n0 = blockIdx.y * 64;
    int wrow = warp * 16;
    int n_lo = n0 + wrow + qr;

    const __half* khp = g_k   + (size_t)bh*Mm*64;
    const __half* vhp = g_vhi + (size_t)bh*64*Mm;
    const __half* vlp = g_vlo + (size_t)bh*64*Mm;

    // preload Q fragments (fp16 hi/lo) for this warp's 16 rows, all 64 dh
    uint32_t q_hi[4][4], q_lo[4][4];
    {
        const __half* qh = g_qhi + ((size_t)bh*Nn + n_lo)*64;
        const __half* ql = g_qlo + ((size_t)bh*Nn + n_lo)*64;
#pragma unroll
        for (int ks = 0; ks < 4; ks++) {
            int kb = ks*16 + qc2;
            q_hi[ks][0] = *(const uint32_t*)&qh[kb];
            q_hi[ks][1] = *(const uint32_t*)&qh[8*64 + kb];
            q_hi[ks][2] = *(const uint32_t*)&qh[kb + 8];
            q_hi[ks][3] = *(const uint32_t*)&qh[8*64 + kb + 8];
            q_lo[ks][0] = *(const uint32_t*)&ql[kb];
            q_lo[ks][1] = *(const uint32_t*)&ql[8*64 + kb];
            q_lo[ks][2] = *(const uint32_t*)&ql[kb + 8];
            q_lo[ks][3] = *(const uint32_t*)&ql[8*64 + kb + 8];
        }
    }

    float hid[8][4];
#pragma unroll
    for (int nf = 0; nf < 8; nf++)
#pragma unroll
        for (int e = 0; e < 4; e++) hid[nf][e] = 0.0f;
    float rs_lo = 0.0f, rs_hi = 0.0f;

    size_t af_lo_row = ((size_t)b*Nn + n_lo)*Mm;
    size_t af_hi_row = af_lo_row + (size_t)8*Mm;
    size_t at_lo_row = ((size_t)bh*Nn + n_lo)*Mm;
    size_t at_hi_row = at_lo_row + (size_t)8*Mm;

    // ---- async stage of one 64-m chunk into buffer `buf` ----
    auto stage = [&](int buf, int m0) {
#pragma unroll
        for (int i = tid; i < 512; i += 128) {
            int r = i >> 3, c8 = (i & 7) * 8;
            cpa16(&Ks[buf][r][c8],  khp + (size_t)(m0 + r)*64 + c8);
            cpa16(&Vth[buf][r][c8], vhp + (size_t)r*Mm + m0 + c8);
            cpa16(&Vtl[buf][r][c8], vlp + (size_t)r*Mm + m0 + c8);
        }
        if (tid < 16) cpa16(&s_km[buf*64 + tid*4], kmask + b*Mm + m0 + tid*4);
        asm volatile("cp.async.commit_group;" ::: "memory");
    };

    stage(0, 0);

#pragma unroll 1
    for (int c = 0; c < 32; c++) {
        int buf = c & 1;
        int m0 = c * 64;
        asm volatile("cp.async.wait_group 0;" ::: "memory");   // stage(c) done
        __syncthreads();   // all warps finished reading buf (c+1)&1 at iter c-1
        if (c + 1 < 32) stage(buf ^ 1, m0 + 64);

#pragma unroll
        for (int half = 0; half < 2; half++) {
            // QK^T for this 32-m half: 2 MMAs per fragment (q hi/lo x k single)
            float sc[4][4];
#pragma unroll
            for (int nfh = 0; nfh < 4; nfh++)
#pragma unroll
                for (int e = 0; e < 4; e++) sc[nfh][e] = 0.0f;
#pragma unroll
            for (int ks = 0; ks < 4; ks++) {
                int kb = ks*16 + qc2;
#pragma unroll
                for (int nfh = 0; nfh < 4; nfh++) {
                    int mc = half*32 + nfh*8 + qr;
                    uint32_t bk[2];
                    bk[0] = *(const uint32_t*)&Ks[buf][mc][kb];
                    bk[1] = *(const uint32_t*)&Ks[buf][mc][kb+8];
                    mma_f16(sc[nfh], q_hi[ks], bk);
                    mma_f16(sc[nfh], q_lo[ks], bk);
                }
            }

            // epilogue: p = mask ? 0 : 2^(s*af);  store fp32 p; pack single-fp16 p frags
            uint32_t pa[2][4];
#pragma unroll
            for (int nfh = 0; nfh < 4; nfh++) {
                int ml = half*32 + nfh*8 + qc2;
                float2 afl = *(const float2*)&af[af_lo_row + m0 + ml];
                float2 afh = *(const float2*)&af[af_hi_row + m0 + ml];
                int2 aml = *(const int2*)&amask[af_lo_row + m0 + ml];
                int2 amh = *(const int2*)&amask[af_hi_row + m0 + ml];
                int km0 = s_km[buf*64 + ml], km1 = s_km[buf*64 + ml + 1];
                float p0 = (km0 | aml.x) ? 0.0f : ex2f(sc[nfh][0] * afl.x);
                float p1 = (km1 | aml.y) ? 0.0f : ex2f(sc[nfh][1] * afl.y);
                float p2 = (km0 | amh.x) ? 0.0f : ex2f(sc[nfh][2] * afh.x);
                float p3 = (km1 | amh.y) ? 0.0f : ex2f(sc[nfh][3] * afh.y);
                rs_lo += p0 + p1;
                rs_hi += p2 + p3;
                *(float2*)&out_attn[at_lo_row + m0 + ml] = make_float2(p0, p1);
                *(float2*)&out_attn[at_hi_row + m0 + ml] = make_float2(p2, p3);
                int ksl = nfh >> 1, hf = (nfh & 1) * 2;
                pa[ksl][hf+0] = pk2h(__float2half_rn(p0), __float2half_rn(p1));
                pa[ksl][hf+1] = pk2h(__float2half_rn(p2), __float2half_rn(p3));
            }

            // AV for this half: 2 MMAs per fragment (p single x V hi/lo)
#pragma unroll
            for (int ksl = 0; ksl < 2; ksl++) {
                int mr = half*32 + ksl*16 + qc2;
#pragma unroll
                for (int nf = 0; nf < 8; nf++) {
                    int dc = nf*8 + qr;
                    uint32_t bvh[2], bvl[2];
                    bvh[0] = *(const uint32_t*)&Vth[buf][dc][mr];
                    bvh[1] = *(const uint32_t*)&Vth[buf][dc][mr+8];
                    bvl[0] = *(const uint32_t*)&Vtl[buf][dc][mr];
                    bvl[1] = *(const uint32_t*)&Vtl[buf][dc][mr+8];
                    mma_f16(hid[nf], pa[ksl], bvh);
                    mma_f16(hid[nf], pa[ksl], bvl);
                }
            }
        }
    }

    // rowsum reduce across the quad, write inverse, write normalized hidden
    rs_lo += __shfl_xor_sync(0xffffffffu, rs_lo, 1);
    rs_lo += __shfl_xor_sync(0xffffffffu, rs_lo, 2);
    rs_hi += __shfl_xor_sync(0xffffffffu, rs_hi, 1);
    rs_hi += __shfl_xor_sync(0xffffffffu, rs_hi, 2);
    float inv_lo = 1.0f / rs_lo;
    float inv_hi = 1.0f / rs_hi;
    if ((lane & 3) == 0) {
        g_inv[(size_t)bh*Nn + n_lo]     = inv_lo;
        g_inv[(size_t)bh*Nn + n_lo + 8] = inv_hi;
    }
#pragma unroll
    for (int nf = 0; nf < 8; nf++) {
        int d = nf*8 + qc2;
        size_t o_lo = ((size_t)b*Nn + n_lo)*Cc + h*64 + d;
        size_t o_hi = o_lo + (size_t)8*Cc;
        *(float2*)&out_hidden[o_lo] = make_float2(hid[nf][0]*inv_lo, hid[nf][1]*inv_lo);
        *(float2*)&out_hidden[o_hi] = make_float2(hid[nf][2]*inv_hi, hid[nf][3]*inv_hi);
    }
}

// ---------------- K3: normalize attn in place (MLP=4) ----------------
// grid: 32768 x 256; each thread scales 4 strided float4s.
__global__ __launch_bounds__(256) void norm_kernel(float4* __restrict__ attn4) {
    int base = blockIdx.x * 1024 + threadIdx.x;
    float4 v0 = attn4[base];
    float4 v1 = attn4[base + 256];
    float4 v2 = attn4[base + 512];
    float4 v3 = attn4[base + 768];
    float i0 = g_inv[(base)       >> 9];
    float i1 = g_inv[(base + 256) >> 9];
    float i2 = g_inv[(base + 512) >> 9];
    float i3 = g_inv[(base + 768) >> 9];
    v0.x *= i0; v0.y *= i0; v0.z *= i0; v0.w *= i0;
    v1.x *= i1; v1.y *= i1; v1.z *= i1; v1.w *= i1;
    v2.x *= i2; v2.y *= i2; v2.z *= i2; v2.w *= i2;
    v3.x *= i3; v3.y *= i3; v3.z *= i3; v3.w *= i3;
    attn4[base]       = v0;
    attn4[base + 256] = v1;
    attn4[base + 512] = v2;
    attn4[base + 768] = v3;
}

// ---------------- launch ----------------
extern "C" void kernel_launch(void* const* d_in, const int* in_sizes, int n_in,
                              void* d_out, int out_size) {
    const float* xq    = (const float*)d_in[0];
    const float* xk    = (const float*)d_in[1];
    const float* xv    = (const float*)d_in[2];
    const float* kw    = (const float*)d_in[3];
    const int*   kmask = (const int*)d_in[4];
    const float* af    = (const float*)d_in[5];
    const int*   amask = (const int*)d_in[6];
    const float* Wq    = (const float*)d_in[7];
    const float* bq    = (const float*)d_in[8];
    const float* Wk    = (const float*)d_in[9];
    const float* bk    = (const float*)d_in[10];
    const float* Wv    = (const float*)d_in[11];
    const float* bv    = (const float*)d_in[12];

    float* out_hidden = (float*)d_out;
    float* out_attn   = out_hidden + (size_t)Bb*Nn*Cc;

    const int attn_smem = 3*NSTG*TILE_B + NSTG*64*(int)sizeof(int);   // 55,808 B
    cudaFuncSetAttribute(attn_kernel, cudaFuncAttributeMaxDynamicSharedMemorySize, attn_smem);

    proj_kernel<<<dim3(64, 8, 3), 256>>>(xq, xk, xv, Wq, bq, Wk, bk, Wv, bv, kw);
    attn_kernel<<<dim3(8, 32, 4), 128, attn_smem>>>(kmask, af, amask, out_hidden, out_attn);
    norm_kernel<<<32768, 256>>>((float4*)out_attn);
}

// round 17
// speedup vs baseline: 1.2568x; 1.2568x over previous
#include <cuda_runtime.h>
#include <cuda_bf16.h>
#include <cuda_fp16.h>
#include <stdint.h>

#define Bb 4
#define Nn 2048
#define Mm 2048
#define Cc 512
#define Hh 8
#define DHd 64
#define LOG2E 1.4426950408889634f

// ---------------- static scratch (no allocations allowed) ----------------
__device__ __half g_qhi[Bb*Hh*Nn*DHd];   // [bh][n][dh], fp16 hi, pre-scaled by 1/8
__device__ __half g_qlo[Bb*Hh*Nn*DHd];   // fp16 lo
__device__ __half g_k  [Bb*Hh*Mm*DHd];   // [bh][m][dh], SINGLE fp16, pre-scaled kw*log2e
__device__ __half g_v  [Bb*Hh*DHd*Mm];   // TRANSPOSED [bh][dh][m], SINGLE fp16
__device__ float  g_inv[Bb*Hh*Nn];       // 1/rowsum

// ---------------- helpers ----------------
__device__ __forceinline__ void mma_bf16(float c[4], const uint32_t a[4], const uint32_t b[2]) {
    asm volatile(
        "mma.sync.aligned.m16n8k16.row.col.f32.bf16.bf16.f32 "
        "{%0,%1,%2,%3}, {%4,%5,%6,%7}, {%8,%9}, {%0,%1,%2,%3};\n"
        : "+f"(c[0]), "+f"(c[1]), "+f"(c[2]), "+f"(c[3])
        : "r"(a[0]), "r"(a[1]), "r"(a[2]), "r"(a[3]), "r"(b[0]), "r"(b[1]));
}

__device__ __forceinline__ void mma_f16(float c[4], const uint32_t a[4], const uint32_t b[2]) {
    asm volatile(
        "mma.sync.aligned.m16n8k16.row.col.f32.f16.f16.f32 "
        "{%0,%1,%2,%3}, {%4,%5,%6,%7}, {%8,%9}, {%0,%1,%2,%3};\n"
        : "+f"(c[0]), "+f"(c[1]), "+f"(c[2]), "+f"(c[3])
        : "r"(a[0]), "r"(a[1]), "r"(a[2]), "r"(a[3]), "r"(b[0]), "r"(b[1]));
}

__device__ __forceinline__ void split2(float x, __nv_bfloat16 &hi, __nv_bfloat16 &lo) {
    hi = __float2bfloat16_rn(x);
    lo = __float2bfloat16_rn(x - __bfloat162float(hi));
}

__device__ __forceinline__ void split2h(float x, __half &hi, __half &lo) {
    hi = __float2half_rn(x);
    lo = __float2half_rn(x - __half2float(hi));
}

__device__ __forceinline__ uint32_t pk2(__nv_bfloat16 a, __nv_bfloat16 b) {
    return (uint32_t)__bfloat16_as_ushort(a) | ((uint32_t)__bfloat16_as_ushort(b) << 16);
}

__device__ __forceinline__ uint32_t pk2h(__half a, __half b) {
    return (uint32_t)__half_as_ushort(a) | ((uint32_t)__half_as_ushort(b) << 16);
}

// guaranteed MUFU.EX2
__device__ __forceinline__ float ex2f(float x) {
    float r;
    asm("ex2.approx.ftz.f32 %0, %1;" : "=f"(r) : "f"(x));
    return r;
}

// 16B async copy gmem -> smem (LDGSTS)
__device__ __forceinline__ void cpa16(void* smem, const void* gmem) {
    uint32_t s = (uint32_t)__cvta_generic_to_shared(smem);
    asm volatile("cp.async.cg.shared.global [%0], [%1], 16;" :: "r"(s), "l"(gmem));
}

// ---------------- K1: fused projections (X@W + b), bf16-split mma ----------------
// grid: (64, 8, 3)  block: 256.  Internal GEMM unchanged; outputs fp16-coded.
__global__ __launch_bounds__(256) void proj_kernel(
    const float* __restrict__ xq, const float* __restrict__ xk, const float* __restrict__ xv,
    const float* __restrict__ Wq, const float* __restrict__ bq,
    const float* __restrict__ Wk, const float* __restrict__ bk,
    const float* __restrict__ Wv, const float* __restrict__ bv,
    const float* __restrict__ kw)
{
    const float* X; const float* W; const float* bias;
    int z = blockIdx.z;
    if (z == 0)      { X = xq; W = Wq; bias = bq; }
    else if (z == 1) { X = xk; W = Wk; bias = bk; }
    else             { X = xv; W = Wv; bias = bv; }

    __shared__ __nv_bfloat16 Ahi[128][40], Alo[128][40];   // [row][k], k-chunk 32, pad 8
    __shared__ __nv_bfloat16 Bshi[64][40], Bslo[64][40];   // [col][k] transposed

    int tid = threadIdx.x, lane = tid & 31, warp = tid >> 5;
    int row0 = blockIdx.x * 128;
    int col0 = blockIdx.y * 64;
    int wr = (warp >> 1) * 32, wc = (warp & 1) * 32;
    int qr = lane >> 2, qc2 = (lane & 3) * 2;

    float acc[2][4][4];
#pragma unroll
    for (int m = 0; m < 2; m++)
#pragma unroll
        for (int n = 0; n < 4; n++)
#pragma unroll
            for (int e = 0; e < 4; e++) acc[m][n][e] = 0.0f;

    for (int kc = 0; kc < Cc; kc += 32) {
#pragma unroll
        for (int i = tid; i < 128*8; i += 256) {
            int r = i >> 3, c4 = (i & 7) * 4;
            float4 v = *(const float4*)&X[(size_t)(row0 + r)*Cc + kc + c4];
            __nv_bfloat16 h0,l0,h1,l1,h2,l2,h3,l3;
            split2(v.x, h0, l0); split2(v.y, h1, l1);
            split2(v.z, h2, l2); split2(v.w, h3, l3);
            uint2 th; th.x = pk2(h0,h1); th.y = pk2(h2,h3);
            uint2 tl; tl.x = pk2(l0,l1); tl.y = pk2(l2,l3);
            *(uint2*)&Ahi[r][c4] = th;
            *(uint2*)&Alo[r][c4] = tl;
        }
#pragma unroll
        for (int it = 0; it < 2; it++) {
            int slot = tid + it*256;
            int col = slot & 63, kk0 = (slot >> 6) * 4;
            __nv_bfloat16 h0,l0,h1,l1,h2,l2,h3,l3;
            float v0 = W[(size_t)(kc+kk0+0)*Cc + col0 + col];
            float v1 = W[(size_t)(kc+kk0+1)*Cc + col0 + col];
            float v2 = W[(size_t)(kc+kk0+2)*Cc + col0 + col];
            float v3 = W[(size_t)(kc+kk0+3)*Cc + col0 + col];
            split2(v0, h0, l0); split2(v1, h1, l1);
            split2(v2, h2, l2); split2(v3, h3, l3);
            uint2 th; th.x = pk2(h0,h1); th.y = pk2(h2,h3);
            uint2 tl; tl.x = pk2(l0,l1); tl.y = pk2(l2,l3);
            *(uint2*)&Bshi[col][kk0] = th;
            *(uint2*)&Bslo[col][kk0] = tl;
        }
        __syncthreads();
#pragma unroll
        for (int ks = 0; ks < 2; ks++) {
            int kb = ks*16 + qc2;
            uint32_t a_hi[2][4], a_lo[2][4];
#pragma unroll
            for (int m = 0; m < 2; m++) {
                int r = wr + m*16 + qr;
                a_hi[m][0] = *(const uint32_t*)&Ahi[r][kb];
                a_hi[m][1] = *(const uint32_t*)&Ahi[r+8][kb];
                a_hi[m][2] = *(const uint32_t*)&Ahi[r][kb+8];
                a_hi[m][3] = *(const uint32_t*)&Ahi[r+8][kb+8];
                a_lo[m][0] = *(const uint32_t*)&Alo[r][kb];
                a_lo[m][1] = *(const uint32_t*)&Alo[r+8][kb];
                a_lo[m][2] = *(const uint32_t*)&Alo[r][kb+8];
                a_lo[m][3] = *(const uint32_t*)&Alo[r+8][kb+8];
            }
#pragma unroll
            for (int nf = 0; nf < 4; nf++) {
                int cn = wc + nf*8 + qr;
                uint32_t b_hi[2], b_lo[2];
                b_hi[0] = *(const uint32_t*)&Bshi[cn][kb];
                b_hi[1] = *(const uint32_t*)&Bshi[cn][kb+8];
                b_lo[0] = *(const uint32_t*)&Bslo[cn][kb];
                b_lo[1] = *(const uint32_t*)&Bslo[cn][kb+8];
#pragma unroll
                for (int m = 0; m < 2; m++) {
                    mma_bf16(acc[m][nf], a_hi[m], b_hi);
                    mma_bf16(acc[m][nf], a_hi[m], b_lo);
                    mma_bf16(acc[m][nf], a_lo[m], b_hi);
                }
            }
        }
        __syncthreads();
    }

    int h = blockIdx.y;
#pragma unroll
    for (int m = 0; m < 2; m++) {
#pragma unroll
        for (int e = 0; e < 2; e++) {
            int rg = row0 + wr + m*16 + qr + e*8;
            int bb = rg >> 11, sq = rg & 2047;
            float rsc;
            if (z == 0)      rsc = 0.125f;
            else if (z == 1) rsc = kw[bb*Mm + sq] * LOG2E;
            else             rsc = 1.0f;
#pragma unroll
            for (int nf = 0; nf < 4; nf++) {
                int d = wc + nf*8 + qc2;
                float v0 = (acc[m][nf][e*2+0] + bias[col0+d])   * rsc;
                float v1 = (acc[m][nf][e*2+1] + bias[col0+d+1]) * rsc;
                if (z == 0) {
                    size_t o = ((size_t)((bb*Hh + h)*2048 + sq))*64 + d;
                    __half h0,l0,h1,l1;
                    split2h(v0, h0, l0); split2h(v1, h1, l1);
                    *(uint32_t*)&g_qhi[o] = pk2h(h0, h1);
                    *(uint32_t*)&g_qlo[o] = pk2h(l0, l1);
                } else if (z == 1) {
                    size_t o = ((size_t)((bb*Hh + h)*2048 + sq))*64 + d;
                    *(uint32_t*)&g_k[o] = pk2h(__float2half_rn(v0), __float2half_rn(v1));
                } else {
                    // transposed: [bh][dh][m], single fp16
                    size_t o = ((size_t)((bb*Hh + h)*64 + d))*2048 + sq;
                    g_v[o]        = __float2half_rn(v0);
                    g_v[o + 2048] = __float2half_rn(v1);
                }
            }
        }
    }
}

// ---------------- K2: fused attention, fp16 datapath, 3 CTAs/SM ------
// grid: (h 8, n-blocks 32, b 4) = 1024 CTAs, block 128 (4 warps x 16 rows = 64 q rows).
// QK: q fp16 hi/lo x K single fp16 = 2 MMAs.  AV: p single fp16 x V single fp16 = 1 MMA.
// out_attn still receives fp32 p (attn output precision preserved).
#define TILE_B (64*72*2)        // one [64][72] fp16 buffer = 9216 B
#define NSTG 2
__global__ __launch_bounds__(128, 3) void attn_kernel(
    const int* __restrict__ kmask, const float* __restrict__ af,
    const int* __restrict__ amask,
    float* __restrict__ out_hidden, float* __restrict__ out_attn)
{
    extern __shared__ char dsm[];
    __half (*Ks)[64][72] = (__half(*)[64][72])(dsm);
    __half (*Vt)[64][72] = (__half(*)[64][72])(dsm + NSTG*TILE_B);
    int* s_km = (int*)(dsm + 2*NSTG*TILE_B);      // [NSTG][64]

    int tid = threadIdx.x, lane = tid & 31, warp = tid >> 5;
    int qr = lane >> 2, qc2 = (lane & 3) * 2;
    int h = blockIdx.x, b = blockIdx.z;
    int bh = b*Hh + h;
    int n0 = blockIdx.y * 64;
    int wrow = warp * 16;
    int n_lo = n0 + wrow + qr;

    const __half* khp = g_k + (size_t)bh*Mm*64;
    const __half* vtp = g_v + (size_t)bh*64*Mm;

    // preload Q fragments (fp16 hi/lo) for this warp's 16 rows, all 64 dh
    uint32_t q_hi[4][4], q_lo[4][4];
    {
        const __half* qh = g_qhi + ((size_t)bh*Nn + n_lo)*64;
        const __half* ql = g_qlo + ((size_t)bh*Nn + n_lo)*64;
#pragma unroll
        for (int ks = 0; ks < 4; ks++) {
            int kb = ks*16 + qc2;
            q_hi[ks][0] = *(const uint32_t*)&qh[kb];
            q_hi[ks][1] = *(const uint32_t*)&qh[8*64 + kb];
            q_hi[ks][2] = *(const uint32_t*)&qh[kb + 8];
            q_hi[ks][3] = *(const uint32_t*)&qh[8*64 + kb + 8];
            q_lo[ks][0] = *(const uint32_t*)&ql[kb];
            q_lo[ks][1] = *(const uint32_t*)&ql[8*64 + kb];
            q_lo[ks][2] = *(const uint32_t*)&ql[kb + 8];
            q_lo[ks][3] = *(const uint32_t*)&ql[8*64 + kb + 8];
        }
    }

    float hid[8][4];
#pragma unroll
    for (int nf = 0; nf < 8; nf++)
#pragma unroll
        for (int e = 0; e < 4; e++) hid[nf][e] = 0.0f;
    float rs_lo = 0.0f, rs_hi = 0.0f;

    size_t af_lo_row = ((size_t)b*Nn + n_lo)*Mm;
    size_t af_hi_row = af_lo_row + (size_t)8*Mm;
    size_t at_lo_row = ((size_t)bh*Nn + n_lo)*Mm;
    size_t at_hi_row = at_lo_row + (size_t)8*Mm;

    // ---- async stage of one 64-m chunk into buffer `buf` ----
    auto stage = [&](int buf, int m0) {
#pragma unroll
        for (int i = tid; i < 512; i += 128) {
            int r = i >> 3, c8 = (i & 7) * 8;
            cpa16(&Ks[buf][r][c8], khp + (size_t)(m0 + r)*64 + c8);
            cpa16(&Vt[buf][r][c8], vtp + (size_t)r*Mm + m0 + c8);
        }
        if (tid < 16) cpa16(&s_km[buf*64 + tid*4], kmask + b*Mm + m0 + tid*4);
        asm volatile("cp.async.commit_group;" ::: "memory");
    };

    stage(0, 0);

#pragma unroll 1
    for (int c = 0; c < 32; c++) {
        int buf = c & 1;
        int m0 = c * 64;
        asm volatile("cp.async.wait_group 0;" ::: "memory");   // stage(c) done
        __syncthreads();   // all warps finished reading buf (c+1)&1 at iter c-1
        if (c + 1 < 32) stage(buf ^ 1, m0 + 64);

#pragma unroll
        for (int half = 0; half < 2; half++) {
            // QK^T for this 32-m half: 2 MMAs per fragment (q hi/lo x k single)
            float sc[4][4];
#pragma unroll
            for (int nfh = 0; nfh < 4; nfh++)
#pragma unroll
                for (int e = 0; e < 4; e++) sc[nfh][e] = 0.0f;
#pragma unroll
            for (int ks = 0; ks < 4; ks++) {
                int kb = ks*16 + qc2;
#pragma unroll
                for (int nfh = 0; nfh < 4; nfh++) {
                    int mc = half*32 + nfh*8 + qr;
                    uint32_t bk[2];
                    bk[0] = *(const uint32_t*)&Ks[buf][mc][kb];
                    bk[1] = *(const uint32_t*)&Ks[buf][mc][kb+8];
                    mma_f16(sc[nfh], q_hi[ks], bk);
                    mma_f16(sc[nfh], q_lo[ks], bk);
                }
            }

            // epilogue: p = mask ? 0 : 2^(s*af);  store fp32 p; pack single-fp16 p frags
            uint32_t pa[2][4];
#pragma unroll
            for (int nfh = 0; nfh < 4; nfh++) {
                int ml = half*32 + nfh*8 + qc2;
                float2 afl = *(const float2*)&af[af_lo_row + m0 + ml];
                float2 afh = *(const float2*)&af[af_hi_row + m0 + ml];
                int2 aml = *(const int2*)&amask[af_lo_row + m0 + ml];
                int2 amh = *(const int2*)&amask[af_hi_row + m0 + ml];
                int km0 = s_km[buf*64 + ml], km1 = s_km[buf*64 + ml + 1];
                float p0 = (km0 | aml.x) ? 0.0f : ex2f(sc[nfh][0] * afl.x);
                float p1 = (km1 | aml.y) ? 0.0f : ex2f(sc[nfh][1] * afl.y);
                float p2 = (km0 | amh.x) ? 0.0f : ex2f(sc[nfh][2] * afh.x);
                float p3 = (km1 | amh.y) ? 0.0f : ex2f(sc[nfh][3] * afh.y);
                rs_lo += p0 + p1;
                rs_hi += p2 + p3;
                *(float2*)&out_attn[at_lo_row + m0 + ml] = make_float2(p0, p1);
                *(float2*)&out_attn[at_hi_row + m0 + ml] = make_float2(p2, p3);
                int ksl = nfh >> 1, hf = (nfh & 1) * 2;
                pa[ksl][hf+0] = pk2h(__float2half_rn(p0), __float2half_rn(p1));
                pa[ksl][hf+1] = pk2h(__float2half_rn(p2), __float2half_rn(p3));
            }

            // AV for this half: 1 MMA per fragment (p single x V single)
#pragma unroll
            for (int ksl = 0; ksl < 2; ksl++) {
                int mr = half*32 + ksl*16 + qc2;
#pragma unroll
                for (int nf = 0; nf < 8; nf++) {
                    int dc = nf*8 + qr;
                    uint32_t bv[2];
                    bv[0] = *(const uint32_t*)&Vt[buf][dc][mr];
                    bv[1] = *(const uint32_t*)&Vt[buf][dc][mr+8];
                    mma_f16(hid[nf], pa[ksl], bv);
                }
            }
        }
    }

    // rowsum reduce across the quad, write inverse, write normalized hidden
    rs_lo += __shfl_xor_sync(0xffffffffu, rs_lo, 1);
    rs_lo += __shfl_xor_sync(0xffffffffu, rs_lo, 2);
    rs_hi += __shfl_xor_sync(0xffffffffu, rs_hi, 1);
    rs_hi += __shfl_xor_sync(0xffffffffu, rs_hi, 2);
    float inv_lo = 1.0f / rs_lo;
    float inv_hi = 1.0f / rs_hi;
    if ((lane & 3) == 0) {
        g_inv[(size_t)bh*Nn + n_lo]     = inv_lo;
        g_inv[(size_t)bh*Nn + n_lo + 8] = inv_hi;
    }
#pragma unroll
    for (int nf = 0; nf < 8; nf++) {
        int d = nf*8 + qc2;
        size_t o_lo = ((size_t)b*Nn + n_lo)*Cc + h*64 + d;
        size_t o_hi = o_lo + (size_t)8*Cc;
        *(float2*)&out_hidden[o_lo] = make_float2(hid[nf][0]*inv_lo, hid[nf][1]*inv_lo);
        *(float2*)&out_hidden[o_hi] = make_float2(hid[nf][2]*inv_hi, hid[nf][3]*inv_hi);
    }
}

// ---------------- K3: normalize attn in place (MLP=4) ----------------
// grid: 32768 x 256; each thread scales 4 strided float4s.
__global__ __launch_bounds__(256) void norm_kernel(float4* __restrict__ attn4) {
    int base = blockIdx.x * 1024 + threadIdx.x;
    float4 v0 = attn4[base];
    float4 v1 = attn4[base + 256];
    float4 v2 = attn4[base + 512];
    float4 v3 = attn4[base + 768];
    float i0 = g_inv[(base)       >> 9];
    float i1 = g_inv[(base + 256) >> 9];
    float i2 = g_inv[(base + 512) >> 9];
    float i3 = g_inv[(base + 768) >> 9];
    v0.x *= i0; v0.y *= i0; v0.z *= i0; v0.w *= i0;
    v1.x *= i1; v1.y *= i1; v1.z *= i1; v1.w *= i1;
    v2.x *= i2; v2.y *= i2; v2.z *= i2; v2.w *= i2;
    v3.x *= i3; v3.y *= i3; v3.z *= i3; v3.w *= i3;
    attn4[base]       = v0;
    attn4[base + 256] = v1;
    attn4[base + 512] = v2;
    attn4[base + 768] = v3;
}

// ---------------- launch ----------------
extern "C" void kernel_launch(void* const* d_in, const int* in_sizes, int n_in,
                              void* d_out, int out_size) {
    const float* xq    = (const float*)d_in[0];
    const float* xk    = (const float*)d_in[1];
    const float* xv    = (const float*)d_in[2];
    const float* kw    = (const float*)d_in[3];
    const int*   kmask = (const int*)d_in[4];
    const float* af    = (const float*)d_in[5];
    const int*   amask = (const int*)d_in[6];
    const float* Wq    = (const float*)d_in[7];
    const float* bq    = (const float*)d_in[8];
    const float* Wk    = (const float*)d_in[9];
    const float* bk    = (const float*)d_in[10];
    const float* Wv    = (const float*)d_in[11];
    const float* bv    = (const float*)d_in[12];

    float* out_hidden = (float*)d_out;
    float* out_attn   = out_hidden + (size_t)Bb*Nn*Cc;

    const int attn_smem = 2*NSTG*TILE_B + NSTG*64*(int)sizeof(int);   // 37,376 B
    cudaFuncSetAttribute(attn_kernel, cudaFuncAttributeMaxDynamicSharedMemorySize, attn_smem);

    proj_kernel<<<dim3(64, 8, 3), 256>>>(xq, xk, xv, Wq, bq, Wk, bk, Wv, bv, kw);
    attn_kernel<<<dim3(8, 32, 4), 128, attn_smem>>>(kmask, af, amask, out_hidden, out_attn);
    norm_kernel<<<32768, 256>>>((float4*)out_attn);
}